// round 11
// baseline (speedup 1.0000x reference)
#include <cuda_runtime.h>
#include <cstdint>

#define AA 512      // attention length
#define OUTS 512    // out_size
#define HH 512
#define WW 512
#define CC 3
#define NMAX 32
#define RPT 4       // rows per thread (sample kernel)
#define VPL 16      // values per lane (prep kernel)

// scratch (allocation-free rule: device globals)
__device__ float g_px[NMAX * OUTS];
__device__ float g_py[NMAX * OUTS];

__device__ __forceinline__ float warpSum(float v) {
    #pragma unroll
    for (int o = 16; o; o >>= 1) v += __shfl_xor_sync(0xffffffffu, v, o);
    return v;
}
__device__ __forceinline__ float warpMax(float v) {
    #pragma unroll
    for (int o = 16; o; o >>= 1) v = fmaxf(v, __shfl_xor_sync(0xffffffffu, v, o));
    return v;
}

__device__ __forceinline__ float inv_cdf_one(const float* c, float tk) {
    // searchsorted left: first j with c[j] >= tk.
    // Range [0,512] has size 513 -> needs exactly 10 halvings.
    int l = 0, h = AA;
    #pragma unroll
    for (int it = 0; it < 10; ++it) {
        if (l < h) {
            int m = (l + h) >> 1;
            if (c[m] < tk) l = m + 1; else h = m;
        }
    }
    int j = min(l, AA - 1);
    float cp = (j > 0) ? c[j - 1] : 0.f;
    float dens = c[j] - cp;
    float p = (float)j + (tk - cp) / fmaxf(dens, 1e-6f);
    return 2.f * p / (float)AA - 1.f;
}

// One warp per batch. Each lane owns a contiguous chunk of VPL=16 values in
// registers; all reductions/scans are warp shuffles (no block barriers).
__global__ void __launch_bounds__(32) prep_kernel(const float* __restrict__ attx,
                                                  const float* __restrict__ atty) {
    __shared__ float cx[AA];
    __shared__ float cy[AA];

    int n = blockIdx.x;
    int l = threadIdx.x;            // lane 0..31

    float ax[VPL], ay[VPL];
    const float* ax_in = attx + n * AA + l * VPL;
    const float* ay_in = atty + n * AA + l * VPL;
    #pragma unroll
    for (int k = 0; k < VPL; ++k) {
        ax[k] = __ldg(ax_in + k);
        ay[k] = __ldg(ay_in + k);
    }

    // normalize
    float sx = 0.f, sy = 0.f;
    #pragma unroll
    for (int k = 0; k < VPL; ++k) { sx += ax[k]; sy += ay[k]; }
    float sax = warpSum(sx), say = warpSum(sy);
    float rx = (float)OUTS / sax, ry = (float)OUTS / say;
    #pragma unroll
    for (int k = 0; k < VPL; ++k) { ax[k] *= rx; ay[k] *= ry; }

    const float thr0 = 4.0f * (float)OUTS / (float)AA;  // DENSE*out/A
    #pragma unroll
    for (int it = 0; it < 5; ++it) {
        float mx = -3.4e38f, my = -3.4e38f;
        #pragma unroll
        for (int k = 0; k < VPL; ++k) { mx = fmaxf(mx, ax[k]); my = fmaxf(my, ay[k]); }
        mx = warpMax(mx); my = warpMax(my);
        float tt = fminf(mx, my);
        if (it == 0) tt = fminf(tt, thr0);
        float s2x = 0.f, s2y = 0.f;
        #pragma unroll
        for (int k = 0; k < VPL; ++k) {
            ax[k] = fminf(ax[k], tt); ay[k] = fminf(ay[k], tt);
            s2x += ax[k]; s2y += ay[k];
        }
        float ssx = warpSum(s2x), ssy = warpSum(s2y);
        float dx = ((float)OUTS - ssx) / (float)AA;
        float dy = ((float)OUTS - ssy) / (float)AA;
        #pragma unroll
        for (int k = 0; k < VPL; ++k) { ax[k] += dx; ay[k] += dy; }
    }

    // inclusive scan: local chunk scan + warp-exclusive offset of chunk totals
    float lx[VPL], ly[VPL];
    float accx = 0.f, accy = 0.f;
    #pragma unroll
    for (int k = 0; k < VPL; ++k) {
        accx += ax[k]; lx[k] = accx;
        accy += ay[k]; ly[k] = accy;
    }
    float inclx = accx, incly = accy;
    #pragma unroll
    for (int o = 1; o < 32; o <<= 1) {
        float tx2 = __shfl_up_sync(0xffffffffu, inclx, o);
        float ty2 = __shfl_up_sync(0xffffffffu, incly, o);
        if (l >= o) { inclx += tx2; incly += ty2; }
    }
    float exclx = inclx - accx, excly = incly - accy;
    float totx = __shfl_sync(0xffffffffu, inclx, 31);
    float toty = __shfl_sync(0xffffffffu, incly, 31);
    #pragma unroll
    for (int k = 0; k < VPL; ++k) {
        cx[l * VPL + k] = lx[k] + exclx;
        cy[l * VPL + k] = ly[k] + excly;
    }
    __syncwarp();

    float stepx = totx / (float)OUTS;
    float stepy = toty / (float)OUTS;

    // 16 searches per lane; output index o = k*32 + l so writes are coalesced
    #pragma unroll
    for (int k = 0; k < VPL; ++k) {
        int o = k * 32 + l;
        float tkx = ((float)o + 0.5f) * stepx;
        float tky = ((float)o + 0.5f) * stepy;
        g_px[n * OUTS + o] = inv_cdf_one(cx, tkx);
        g_py[n * OUTS + o] = inv_cdf_one(cy, tky);
    }
}

// Deep-MLP sampler (R9 shape): 128-thread CTAs, each thread owns one px column
// j and RPT=4 consecutive output rows; all 48 gathers batched. Outputs stored
// with __stcs (streaming, evict-first) so the 168 MB write stream does not
// evict the input images from L2.
// grid: (WW/128 jtiles, OUTS/RPT row tiles, N)
__global__ void __launch_bounds__(128) sample_kernel(const float* __restrict__ data,
                                                     float* __restrict__ out_s,
                                                     float2* __restrict__ out_g) {
    int tx = threadIdx.x;                    // 0..127
    int j = blockIdx.x * 128 + tx;           // output column
    int i0 = blockIdx.y * RPT;               // first output row
    int n = blockIdx.z;

    // px coords (once per thread)
    float px = __ldg(&g_px[n * OUTS + j]);
    float ix = (px + 1.f) * 0.5f * (float)(WW - 1);
    float fx = floorf(ix);
    float wx = ix - fx;
    int x0 = min(max((int)fx, 0), WW - 1);
    int x1 = min(x0 + 1, WW - 1);
    float omwx = 1.f - wx;

    // py coords for RPT rows (one vectorized load; i0 is 4-aligned)
    float4 py4 = __ldg((const float4*)&g_py[n * OUTS + i0]);
    float pyv[RPT] = {py4.x, py4.y, py4.z, py4.w};
    float wy[RPT];
    int y0[RPT], y1[RPT];
    #pragma unroll
    for (int r = 0; r < RPT; ++r) {
        float iy = (pyv[r] + 1.f) * 0.5f * (float)(HH - 1);
        float fy = floorf(iy);
        wy[r] = iy - fy;
        int yy0 = min(max((int)fy, 0), HH - 1);
        y0[r] = yy0;
        y1[r] = min(yy0 + 1, HH - 1);
    }

    const float* img = data + (size_t)n * CC * HH * WW;

    // batch-issue all 48 gathers before any consumption
    float v00[RPT][CC], v01[RPT][CC], v10[RPT][CC], v11[RPT][CC];
    #pragma unroll
    for (int r = 0; r < RPT; ++r) {
        #pragma unroll
        for (int c = 0; c < CC; ++c) {
            const float* ch = img + (size_t)c * HH * WW;
            const float* r0p = ch + (size_t)y0[r] * WW;
            const float* r1p = ch + (size_t)y1[r] * WW;
            v00[r][c] = __ldg(r0p + x0);
            v01[r][c] = __ldg(r0p + x1);
            v10[r][c] = __ldg(r1p + x0);
            v11[r][c] = __ldg(r1p + x1);
        }
    }

    // combine + streaming stores (coalesced: consecutive tx -> consecutive j)
    #pragma unroll
    for (int c = 0; c < CC; ++c) {
        float* o = out_s + (((size_t)n * CC + c) * HH + i0) * WW + j;
        #pragma unroll
        for (int r = 0; r < RPT; ++r) {
            float top = v00[r][c] * omwx + v01[r][c] * wx;
            float bot = v10[r][c] * omwx + v11[r][c] * wx;
            __stcs(o + (size_t)r * WW, top * (1.f - wy[r]) + bot * wy[r]);
        }
    }

    float2* g = out_g + ((size_t)n * OUTS + i0) * OUTS + j;
    #pragma unroll
    for (int r = 0; r < RPT; ++r)
        __stcs(g + (size_t)r * OUTS, make_float2(px, pyv[r]));
}

extern "C" void kernel_launch(void* const* d_in, const int* in_sizes, int n_in,
                              void* d_out, int out_size) {
    const float* data = (const float*)d_in[0];
    const float* attx = (const float*)d_in[1];
    const float* atty = (const float*)d_in[2];

    int N = in_sizes[1] / AA;   // attx is (N, 512, 1)

    float* out = (float*)d_out;
    float* out_s = out;                                        // (N, C, 512, 512)
    float2* out_g = (float2*)(out + (size_t)N * CC * HH * WW); // (N, 512, 512, 2)

    prep_kernel<<<N, 32>>>(attx, atty);
    dim3 block(128);
    dim3 grid(WW / 128, OUTS / RPT, N);
    sample_kernel<<<grid, block>>>(data, out_s, out_g);
}

// round 13
// speedup vs baseline: 1.1645x; 1.1645x over previous
#include <cuda_runtime.h>
#include <cstdint>

#define AA 512      // attention length
#define OUTS 512    // out_size
#define HH 512
#define WW 512
#define CC 3
#define NMAX 32
#define RPT 4       // rows per thread (sample kernel)

// scratch (allocation-free rule: device globals)
__device__ float g_px[NMAX * OUTS];
__device__ float g_py[NMAX * OUTS];

__device__ __forceinline__ float warpSum(float v) {
    #pragma unroll
    for (int o = 16; o; o >>= 1) v += __shfl_xor_sync(0xffffffffu, v, o);
    return v;
}
__device__ __forceinline__ float warpMax(float v) {
    #pragma unroll
    for (int o = 16; o; o >>= 1) v = fmaxf(v, __shfl_xor_sync(0xffffffffu, v, o));
    return v;
}

// fused block reductions for two values (512 threads), one barrier pair each
__device__ void blockSum2(float a, float b, volatile float* sbuf, float* ra, float* rb) {
    int lane = threadIdx.x & 31, w = threadIdx.x >> 5;
    a = warpSum(a); b = warpSum(b);
    if (lane == 0) { sbuf[w] = a; sbuf[32 + w] = b; }
    __syncthreads();
    if (w == 0) {
        float x = (lane < 16) ? sbuf[lane] : 0.f;
        float y = (lane < 16) ? sbuf[32 + lane] : 0.f;
        x = warpSum(x); y = warpSum(y);
        if (lane == 0) { sbuf[0] = x; sbuf[32] = y; }
    }
    __syncthreads();
    *ra = sbuf[0]; *rb = sbuf[32];
    __syncthreads();
}

__device__ void blockMax2(float a, float b, volatile float* sbuf, float* ra, float* rb) {
    int lane = threadIdx.x & 31, w = threadIdx.x >> 5;
    a = warpMax(a); b = warpMax(b);
    if (lane == 0) { sbuf[w] = a; sbuf[32 + w] = b; }
    __syncthreads();
    if (w == 0) {
        float x = (lane < 16) ? sbuf[lane] : -3.4e38f;
        float y = (lane < 16) ? sbuf[32 + lane] : -3.4e38f;
        x = warpMax(x); y = warpMax(y);
        if (lane == 0) { sbuf[0] = x; sbuf[32] = y; }
    }
    __syncthreads();
    *ra = sbuf[0]; *rb = sbuf[32];
    __syncthreads();
}

// fused inclusive block scan of two 512-value sequences -> outa[tid], outb[tid]
__device__ void blockScan2(float a, float b, float* outa, float* outb, volatile float* sbuf) {
    int lane = threadIdx.x & 31, w = threadIdx.x >> 5;
    float sa = a, sb = b;
    #pragma unroll
    for (int o = 1; o < 32; o <<= 1) {
        float ta = __shfl_up_sync(0xffffffffu, sa, o);
        float tb = __shfl_up_sync(0xffffffffu, sb, o);
        if (lane >= o) { sa += ta; sb += tb; }
    }
    if (lane == 31) { sbuf[w] = sa; sbuf[32 + w] = sb; }
    __syncthreads();
    if (w == 0 && lane < 16) {
        float wa = sbuf[lane], wb = sbuf[32 + lane];
        #pragma unroll
        for (int o = 1; o < 16; o <<= 1) {
            float ta = __shfl_up_sync(0x0000ffffu, wa, o);
            float tb = __shfl_up_sync(0x0000ffffu, wb, o);
            if (lane >= o) { wa += ta; wb += tb; }
        }
        sbuf[lane] = wa; sbuf[32 + lane] = wb;
    }
    __syncthreads();
    float offa = (w > 0) ? sbuf[w - 1] : 0.f;
    float offb = (w > 0) ? sbuf[32 + w - 1] : 0.f;
    outa[threadIdx.x] = sa + offa;
    outb[threadIdx.x] = sb + offb;
    __syncthreads();
}

__device__ __forceinline__ float inv_cdf_one(const float* c, float tk) {
    // searchsorted left: first j with c[j] >= tk.
    // Range [0,512] has size 513 -> needs exactly 10 halvings.
    int l = 0, h = AA;
    #pragma unroll
    for (int it = 0; it < 10; ++it) {
        if (l < h) {
            int m = (l + h) >> 1;
            if (c[m] < tk) l = m + 1; else h = m;
        }
    }
    int j = min(l, AA - 1);
    float cp = (j > 0) ? c[j - 1] : 0.f;
    float dens = c[j] - cp;
    float p = (float)j + (tk - cp) / fmaxf(dens, 1e-6f);
    return 2.f * p / (float)AA - 1.f;
}

__global__ void __launch_bounds__(512) prep_kernel(const float* __restrict__ attx,
                                                   const float* __restrict__ atty) {
    __shared__ float sbuf[64];
    __shared__ float cx[AA];
    __shared__ float cy[AA];
    int n = blockIdx.x;
    int t = threadIdx.x;

    float ax = attx[n * AA + t];
    float ay = atty[n * AA + t];

    float sax, say;
    blockSum2(ax, ay, sbuf, &sax, &say);
    ax = ax / sax * (float)OUTS;
    ay = ay / say * (float)OUTS;

    const float thr0 = 4.0f * (float)OUTS / (float)AA;  // DENSE*out/A
    #pragma unroll
    for (int it = 0; it < 5; ++it) {
        float mx, my;
        blockMax2(ax, ay, sbuf, &mx, &my);
        float tt = fminf(mx, my);
        if (it == 0) tt = fminf(tt, thr0);
        ax = fminf(ax, tt);
        ay = fminf(ay, tt);
        blockSum2(ax, ay, sbuf, &sax, &say);
        ax += ((float)OUTS - sax) / (float)AA;
        ay += ((float)OUTS - say) / (float)AA;
    }

    blockScan2(ax, ay, cx, cy, sbuf);

    float stepx = cx[AA - 1] / (float)OUTS;
    float stepy = cy[AA - 1] / (float)OUTS;
    float tkx = ((float)t + 0.5f) * stepx;
    float tky = ((float)t + 0.5f) * stepy;

    g_px[n * OUTS + t] = inv_cdf_one(cx, tkx);
    g_py[n * OUTS + t] = inv_cdf_one(cy, tky);
}

// read-only load with L2 evict-last policy via createpolicy + cache_hint
__device__ __forceinline__ float ldg_el(const float* p, uint64_t pol) {
    float v;
    asm volatile("ld.global.nc.L2::cache_hint.f32 %0, [%1], %2;"
                 : "=f"(v) : "l"(p), "l"(pol));
    return v;
}

// Deep-MLP sampler (R9 shape): 128-thread CTAs, each thread owns one px column
// j and RPT=4 consecutive output rows; all 48 gathers batched. Input gathers use
// L2 evict_last policy (pin 96 MB image set in 126 MB L2); output stores use
// __stcs (evict-first streaming) so the 168 MB write stream passes through.
// grid: (WW/128 jtiles, OUTS/RPT row tiles, N)
__global__ void __launch_bounds__(128) sample_kernel(const float* __restrict__ data,
                                                     float* __restrict__ out_s,
                                                     float2* __restrict__ out_g) {
    uint64_t pol;
    asm volatile("createpolicy.fractional.L2::evict_last.b64 %0, 1.0;" : "=l"(pol));

    int tx = threadIdx.x;                    // 0..127
    int j = blockIdx.x * 128 + tx;           // output column
    int i0 = blockIdx.y * RPT;               // first output row
    int n = blockIdx.z;

    // px coords (once per thread)
    float px = __ldg(&g_px[n * OUTS + j]);
    float ix = (px + 1.f) * 0.5f * (float)(WW - 1);
    float fx = floorf(ix);
    float wx = ix - fx;
    int x0 = min(max((int)fx, 0), WW - 1);
    int x1 = min(x0 + 1, WW - 1);
    float omwx = 1.f - wx;

    // py coords for RPT rows (one vectorized load; i0 is 4-aligned)
    float4 py4 = __ldg((const float4*)&g_py[n * OUTS + i0]);
    float pyv[RPT] = {py4.x, py4.y, py4.z, py4.w};
    float wy[RPT];
    int y0[RPT], y1[RPT];
    #pragma unroll
    for (int r = 0; r < RPT; ++r) {
        float iy = (pyv[r] + 1.f) * 0.5f * (float)(HH - 1);
        float fy = floorf(iy);
        wy[r] = iy - fy;
        int yy0 = min(max((int)fy, 0), HH - 1);
        y0[r] = yy0;
        y1[r] = min(yy0 + 1, HH - 1);
    }

    const float* img = data + (size_t)n * CC * HH * WW;

    // batch-issue all 48 gathers before any consumption
    float v00[RPT][CC], v01[RPT][CC], v10[RPT][CC], v11[RPT][CC];
    #pragma unroll
    for (int r = 0; r < RPT; ++r) {
        #pragma unroll
        for (int c = 0; c < CC; ++c) {
            const float* ch = img + (size_t)c * HH * WW;
            const float* r0p = ch + (size_t)y0[r] * WW;
            const float* r1p = ch + (size_t)y1[r] * WW;
            v00[r][c] = ldg_el(r0p + x0, pol);
            v01[r][c] = ldg_el(r0p + x1, pol);
            v10[r][c] = ldg_el(r1p + x0, pol);
            v11[r][c] = ldg_el(r1p + x1, pol);
        }
    }

    // combine + streaming stores (coalesced: consecutive tx -> consecutive j)
    #pragma unroll
    for (int c = 0; c < CC; ++c) {
        float* o = out_s + (((size_t)n * CC + c) * HH + i0) * WW + j;
        #pragma unroll
        for (int r = 0; r < RPT; ++r) {
            float top = v00[r][c] * omwx + v01[r][c] * wx;
            float bot = v10[r][c] * omwx + v11[r][c] * wx;
            __stcs(o + (size_t)r * WW, top * (1.f - wy[r]) + bot * wy[r]);
        }
    }

    float2* g = out_g + ((size_t)n * OUTS + i0) * OUTS + j;
    #pragma unroll
    for (int r = 0; r < RPT; ++r)
        __stcs(g + (size_t)r * OUTS, make_float2(px, pyv[r]));
}

extern "C" void kernel_launch(void* const* d_in, const int* in_sizes, int n_in,
                              void* d_out, int out_size) {
    const float* data = (const float*)d_in[0];
    const float* attx = (const float*)d_in[1];
    const float* atty = (const float*)d_in[2];

    int N = in_sizes[1] / AA;   // attx is (N, 512, 1)

    float* out = (float*)d_out;
    float* out_s = out;                                        // (N, C, 512, 512)
    float2* out_g = (float2*)(out + (size_t)N * CC * HH * WW); // (N, 512, 512, 2)

    prep_kernel<<<N, 512>>>(attx, atty);
    dim3 block(128);
    dim3 grid(WW / 128, OUTS / RPT, N);
    sample_kernel<<<grid, block>>>(data, out_s, out_g);
}

// round 14
// speedup vs baseline: 1.2158x; 1.0441x over previous
#include <cuda_runtime.h>
#include <cstdint>

#define AA 512      // attention length
#define OUTS 512    // out_size
#define HH 512
#define WW 512
#define CC 3
#define NMAX 32
#define RPT 4       // rows per thread (sample kernel)

// scratch (allocation-free rule: device globals)
__device__ float g_px[NMAX * OUTS];
__device__ float g_py[NMAX * OUTS];

__device__ __forceinline__ float warpSum(float v) {
    #pragma unroll
    for (int o = 16; o; o >>= 1) v += __shfl_xor_sync(0xffffffffu, v, o);
    return v;
}
__device__ __forceinline__ float warpMax(float v) {
    #pragma unroll
    for (int o = 16; o; o >>= 1) v = fmaxf(v, __shfl_xor_sync(0xffffffffu, v, o));
    return v;
}

// fused block reductions for two values (512 threads), one barrier pair each
__device__ void blockSum2(float a, float b, volatile float* sbuf, float* ra, float* rb) {
    int lane = threadIdx.x & 31, w = threadIdx.x >> 5;
    a = warpSum(a); b = warpSum(b);
    if (lane == 0) { sbuf[w] = a; sbuf[32 + w] = b; }
    __syncthreads();
    if (w == 0) {
        float x = (lane < 16) ? sbuf[lane] : 0.f;
        float y = (lane < 16) ? sbuf[32 + lane] : 0.f;
        x = warpSum(x); y = warpSum(y);
        if (lane == 0) { sbuf[0] = x; sbuf[32] = y; }
    }
    __syncthreads();
    *ra = sbuf[0]; *rb = sbuf[32];
    __syncthreads();
}

__device__ void blockMax2(float a, float b, volatile float* sbuf, float* ra, float* rb) {
    int lane = threadIdx.x & 31, w = threadIdx.x >> 5;
    a = warpMax(a); b = warpMax(b);
    if (lane == 0) { sbuf[w] = a; sbuf[32 + w] = b; }
    __syncthreads();
    if (w == 0) {
        float x = (lane < 16) ? sbuf[lane] : -3.4e38f;
        float y = (lane < 16) ? sbuf[32 + lane] : -3.4e38f;
        x = warpMax(x); y = warpMax(y);
        if (lane == 0) { sbuf[0] = x; sbuf[32] = y; }
    }
    __syncthreads();
    *ra = sbuf[0]; *rb = sbuf[32];
    __syncthreads();
}

// fused inclusive block scan of two 512-value sequences -> outa[tid], outb[tid]
__device__ void blockScan2(float a, float b, float* outa, float* outb, volatile float* sbuf) {
    int lane = threadIdx.x & 31, w = threadIdx.x >> 5;
    float sa = a, sb = b;
    #pragma unroll
    for (int o = 1; o < 32; o <<= 1) {
        float ta = __shfl_up_sync(0xffffffffu, sa, o);
        float tb = __shfl_up_sync(0xffffffffu, sb, o);
        if (lane >= o) { sa += ta; sb += tb; }
    }
    if (lane == 31) { sbuf[w] = sa; sbuf[32 + w] = sb; }
    __syncthreads();
    if (w == 0 && lane < 16) {
        float wa = sbuf[lane], wb = sbuf[32 + lane];
        #pragma unroll
        for (int o = 1; o < 16; o <<= 1) {
            float ta = __shfl_up_sync(0x0000ffffu, wa, o);
            float tb = __shfl_up_sync(0x0000ffffu, wb, o);
            if (lane >= o) { wa += ta; wb += tb; }
        }
        sbuf[lane] = wa; sbuf[32 + lane] = wb;
    }
    __syncthreads();
    float offa = (w > 0) ? sbuf[w - 1] : 0.f;
    float offb = (w > 0) ? sbuf[32 + w - 1] : 0.f;
    outa[threadIdx.x] = sa + offa;
    outb[threadIdx.x] = sb + offb;
    __syncthreads();
}

__device__ __forceinline__ float inv_cdf_one(const float* c, float tk) {
    // searchsorted left: first j with c[j] >= tk.
    // Range [0,512] has size 513 -> needs exactly 10 halvings.
    int l = 0, h = AA;
    #pragma unroll
    for (int it = 0; it < 10; ++it) {
        if (l < h) {
            int m = (l + h) >> 1;
            if (c[m] < tk) l = m + 1; else h = m;
        }
    }
    int j = min(l, AA - 1);
    float cp = (j > 0) ? c[j - 1] : 0.f;
    float dens = c[j] - cp;
    float p = (float)j + (tk - cp) / fmaxf(dens, 1e-6f);
    return 2.f * p / (float)AA - 1.f;
}

__global__ void __launch_bounds__(512) prep_kernel(const float* __restrict__ attx,
                                                   const float* __restrict__ atty) {
    __shared__ float sbuf[64];
    __shared__ float cx[AA];
    __shared__ float cy[AA];
    int n = blockIdx.x;
    int t = threadIdx.x;

    float ax = attx[n * AA + t];
    float ay = atty[n * AA + t];

    float sax, say;
    blockSum2(ax, ay, sbuf, &sax, &say);
    ax = ax / sax * (float)OUTS;
    ay = ay / say * (float)OUTS;

    const float thr0 = 4.0f * (float)OUTS / (float)AA;  // DENSE*out/A
    #pragma unroll
    for (int it = 0; it < 5; ++it) {
        float mx, my;
        blockMax2(ax, ay, sbuf, &mx, &my);
        float tt = fminf(mx, my);
        if (it == 0) tt = fminf(tt, thr0);
        ax = fminf(ax, tt);
        ay = fminf(ay, tt);
        blockSum2(ax, ay, sbuf, &sax, &say);
        ax += ((float)OUTS - sax) / (float)AA;
        ay += ((float)OUTS - say) / (float)AA;
    }

    blockScan2(ax, ay, cx, cy, sbuf);

    float stepx = cx[AA - 1] / (float)OUTS;
    float stepy = cy[AA - 1] / (float)OUTS;
    float tkx = ((float)t + 0.5f) * stepx;
    float tky = ((float)t + 0.5f) * stepy;

    g_px[n * OUTS + t] = inv_cdf_one(cx, tkx);
    g_py[n * OUTS + t] = inv_cdf_one(cy, tky);
}

// LSU-floor-optimized sampler: each thread owns 2 CONSECUTIVE px (j0 = 2*(base+tx))
// and RPT=4 rows. Gathers are 12 LDG.32/px (irreducible); sampled stores are
// STG.64 (float2) and grid stores STG.128 (float4) -> per-px LSU issue cost
// drops from 1.43 to ~1.25 cyc/px. __stcs keeps the write stream out of L2.
// grid: (OUTS/256 jtiles, OUTS/RPT rowtiles, N); block 128.
__global__ void __launch_bounds__(128) sample_kernel(const float* __restrict__ data,
                                                     float* __restrict__ out_s,
                                                     float4* __restrict__ out_g) {
    int tx = threadIdx.x;                      // 0..127
    int j0 = (blockIdx.x * 128 + tx) * 2;      // first of 2 consecutive px
    int i0 = blockIdx.y * RPT;                 // first output row
    int n = blockIdx.z;

    // px coords for the 2 pixels (one LDG.64)
    float2 px2 = __ldg((const float2*)&g_px[n * OUTS + j0]);
    float pxv[2] = {px2.x, px2.y};
    int x0[2], x1[2];
    float wx[2];
    #pragma unroll
    for (int q = 0; q < 2; ++q) {
        float ix = (pxv[q] + 1.f) * 0.5f * (float)(WW - 1);
        float fx = floorf(ix);
        wx[q] = ix - fx;
        x0[q] = min(max((int)fx, 0), WW - 1);
        x1[q] = min(x0[q] + 1, WW - 1);
    }

    // py coords for RPT rows (one LDG.128; i0 is 4-aligned)
    float4 py4 = __ldg((const float4*)&g_py[n * OUTS + i0]);
    float pyv[RPT] = {py4.x, py4.y, py4.z, py4.w};
    float wy[RPT];
    int y0[RPT], y1[RPT];
    #pragma unroll
    for (int r = 0; r < RPT; ++r) {
        float iy = (pyv[r] + 1.f) * 0.5f * (float)(HH - 1);
        float fy = floorf(iy);
        wy[r] = iy - fy;
        int yy0 = min(max((int)fy, 0), HH - 1);
        y0[r] = yy0;
        y1[r] = min(yy0 + 1, HH - 1);
    }

    const float* img = data + (size_t)n * CC * HH * WW;

    // process per row: load 24 values (2px x 3c x 4 corners), combine, store.
    // Occupancy (many warps/SM) hides latency; LSU issue floor is the binder.
    #pragma unroll
    for (int r = 0; r < RPT; ++r) {
        float v00[CC][2], v01[CC][2], v10[CC][2], v11[CC][2];
        #pragma unroll
        for (int c = 0; c < CC; ++c) {
            const float* ch = img + (size_t)c * HH * WW;
            const float* r0p = ch + (size_t)y0[r] * WW;
            const float* r1p = ch + (size_t)y1[r] * WW;
            #pragma unroll
            for (int q = 0; q < 2; ++q) {
                v00[c][q] = __ldg(r0p + x0[q]);
                v01[c][q] = __ldg(r0p + x1[q]);
                v10[c][q] = __ldg(r1p + x0[q]);
                v11[c][q] = __ldg(r1p + x1[q]);
            }
        }
        float omwy = 1.f - wy[r];
        #pragma unroll
        for (int c = 0; c < CC; ++c) {
            float res[2];
            #pragma unroll
            for (int q = 0; q < 2; ++q) {
                float omwx = 1.f - wx[q];
                float top = v00[c][q] * omwx + v01[c][q] * wx[q];
                float bot = v10[c][q] * omwx + v11[c][q] * wx[q];
                res[q] = top * omwy + bot * wy[r];
            }
            float* o = out_s + (((size_t)n * CC + c) * HH + i0 + r) * WW + j0;
            __stcs((float2*)o, make_float2(res[0], res[1]));
        }
        float4* g = out_g + (((size_t)n * OUTS + i0 + r) * OUTS + j0) / 2;
        __stcs(g, make_float4(pxv[0], pyv[r], pxv[1], pyv[r]));
    }
}

extern "C" void kernel_launch(void* const* d_in, const int* in_sizes, int n_in,
                              void* d_out, int out_size) {
    const float* data = (const float*)d_in[0];
    const float* attx = (const float*)d_in[1];
    const float* atty = (const float*)d_in[2];

    int N = in_sizes[1] / AA;   // attx is (N, 512, 1)

    float* out = (float*)d_out;
    float* out_s = out;                                        // (N, C, 512, 512)
    float4* out_g = (float4*)(out + (size_t)N * CC * HH * WW); // (N, 512, 512, 2)

    prep_kernel<<<N, 512>>>(attx, atty);
    dim3 block(128);
    dim3 grid(OUTS / 256, OUTS / RPT, N);
    sample_kernel<<<grid, block>>>(data, out_s, out_g);
}

// round 15
// speedup vs baseline: 1.2443x; 1.0234x over previous
#include <cuda_runtime.h>
#include <cstdint>

#define AA 512      // attention length
#define OUTS 512    // out_size
#define HH 512
#define WW 512
#define CC 3
#define NMAX 32
#define RPT 4       // rows per thread (sample kernel)

// scratch (allocation-free rule: device globals)
__device__ float g_px[NMAX * OUTS];
__device__ float g_py[NMAX * OUTS];

__device__ __forceinline__ float warpSum(float v) {
    #pragma unroll
    for (int o = 16; o; o >>= 1) v += __shfl_xor_sync(0xffffffffu, v, o);
    return v;
}
__device__ __forceinline__ float warpMax(float v) {
    #pragma unroll
    for (int o = 16; o; o >>= 1) v = fmaxf(v, __shfl_xor_sync(0xffffffffu, v, o));
    return v;
}

// fused block reduction: sums of (a,b) and maxes of (c,d), one barrier round
__device__ void blockRed4(float a, float b, float c, float d, volatile float* sbuf,
                          float* ra, float* rb, float* rc, float* rd) {
    int lane = threadIdx.x & 31, w = threadIdx.x >> 5;
    a = warpSum(a); b = warpSum(b); c = warpMax(c); d = warpMax(d);
    if (lane == 0) { sbuf[w] = a; sbuf[32 + w] = b; sbuf[64 + w] = c; sbuf[96 + w] = d; }
    __syncthreads();
    if (w == 0) {
        float x = (lane < 16) ? sbuf[lane] : 0.f;
        float y = (lane < 16) ? sbuf[32 + lane] : 0.f;
        float z = (lane < 16) ? sbuf[64 + lane] : -3.4e38f;
        float u = (lane < 16) ? sbuf[96 + lane] : -3.4e38f;
        x = warpSum(x); y = warpSum(y); z = warpMax(z); u = warpMax(u);
        if (lane == 0) { sbuf[0] = x; sbuf[32] = y; sbuf[64] = z; sbuf[96] = u; }
    }
    __syncthreads();
    *ra = sbuf[0]; *rb = sbuf[32]; *rc = sbuf[64]; *rd = sbuf[96];
    __syncthreads();
}

// fused block sum of two values (512 threads), one barrier round
__device__ void blockSum2(float a, float b, volatile float* sbuf, float* ra, float* rb) {
    int lane = threadIdx.x & 31, w = threadIdx.x >> 5;
    a = warpSum(a); b = warpSum(b);
    if (lane == 0) { sbuf[w] = a; sbuf[32 + w] = b; }
    __syncthreads();
    if (w == 0) {
        float x = (lane < 16) ? sbuf[lane] : 0.f;
        float y = (lane < 16) ? sbuf[32 + lane] : 0.f;
        x = warpSum(x); y = warpSum(y);
        if (lane == 0) { sbuf[0] = x; sbuf[32] = y; }
    }
    __syncthreads();
    *ra = sbuf[0]; *rb = sbuf[32];
    __syncthreads();
}

// fused inclusive block scan of two 512-value sequences -> outa[tid], outb[tid]
__device__ void blockScan2(float a, float b, float* outa, float* outb, volatile float* sbuf) {
    int lane = threadIdx.x & 31, w = threadIdx.x >> 5;
    float sa = a, sb = b;
    #pragma unroll
    for (int o = 1; o < 32; o <<= 1) {
        float ta = __shfl_up_sync(0xffffffffu, sa, o);
        float tb = __shfl_up_sync(0xffffffffu, sb, o);
        if (lane >= o) { sa += ta; sb += tb; }
    }
    if (lane == 31) { sbuf[w] = sa; sbuf[32 + w] = sb; }
    __syncthreads();
    if (w == 0 && lane < 16) {
        float wa = sbuf[lane], wb = sbuf[32 + lane];
        #pragma unroll
        for (int o = 1; o < 16; o <<= 1) {
            float ta = __shfl_up_sync(0x0000ffffu, wa, o);
            float tb = __shfl_up_sync(0x0000ffffu, wb, o);
            if (lane >= o) { wa += ta; wb += tb; }
        }
        sbuf[lane] = wa; sbuf[32 + lane] = wb;
    }
    __syncthreads();
    float offa = (w > 0) ? sbuf[w - 1] : 0.f;
    float offb = (w > 0) ? sbuf[32 + w - 1] : 0.f;
    outa[threadIdx.x] = sa + offa;
    outb[threadIdx.x] = sb + offb;
    __syncthreads();
}

// searchsorted-left on corrected cdf c_eff[m] = c[m] + (m+1)*dcor
__device__ __forceinline__ float inv_cdf_one(const float* c, float tk, float dcor) {
    int l = 0, h = AA;
    #pragma unroll
    for (int it = 0; it < 10; ++it) {
        if (l < h) {
            int m = (l + h) >> 1;
            float cm = c[m] + (float)(m + 1) * dcor;
            if (cm < tk) l = m + 1; else h = m;
        }
    }
    int j = min(l, AA - 1);
    float cp = (j > 0) ? (c[j - 1] + (float)j * dcor) : 0.f;
    float cj = c[j] + (float)(j + 1) * dcor;
    float dens = cj - cp;
    float p = (float)j + (tk - cp) / fmaxf(dens, 1e-6f);
    return 2.f * p / (float)AA - 1.f;
}

// prep with analytic max tracking: 6 barrier rounds total
// (1 fused sum+max, 4 sums, 1 scan); final renorm folded into the
// cumsum correction c_eff[i] = scan(clip)[i] + (i+1)*dx.
__global__ void __launch_bounds__(512) prep_kernel(const float* __restrict__ attx,
                                                   const float* __restrict__ atty) {
    __shared__ float sbuf[128];
    __shared__ float cx[AA];
    __shared__ float cy[AA];
    int n = blockIdx.x;
    int t = threadIdx.x;

    float ax = attx[n * AA + t];
    float ay = atty[n * AA + t];

    float sax, say, mxx, mxy;
    blockRed4(ax, ay, ax, ay, sbuf, &sax, &say, &mxx, &mxy);
    ax = ax / sax * (float)OUTS;
    ay = ay / say * (float)OUTS;
    mxx = mxx / sax * (float)OUTS;   // exact: division/mult monotone, attained at argmax
    mxy = mxy / say * (float)OUTS;

    const float thr0 = 4.0f * (float)OUTS / (float)AA;  // DENSE*out/A
    #pragma unroll
    for (int it = 0; it < 5; ++it) {
        float tt = fminf(mxx, mxy);
        if (it == 0) tt = fminf(tt, thr0);
        ax = fminf(ax, tt);
        ay = fminf(ay, tt);
        if (it < 4) {
            float ssx, ssy;
            blockSum2(ax, ay, sbuf, &ssx, &ssy);
            float dx = ((float)OUTS - ssx) / (float)AA;
            float dy = ((float)OUTS - ssy) / (float)AA;
            ax += dx; ay += dy;
            mxx = fminf(mxx, tt) + dx;   // exact analytic max update
            mxy = fminf(mxy, tt) + dy;
        }
    }

    // scan of CLIPPED values (5th renorm folded in via dx correction)
    blockScan2(ax, ay, cx, cy, sbuf);
    float dx = ((float)OUTS - cx[AA - 1]) / (float)AA;
    float dy = ((float)OUTS - cy[AA - 1]) / (float)AA;
    float totx = cx[AA - 1] + (float)AA * dx;
    float toty = cy[AA - 1] + (float)AA * dy;

    float stepx = totx / (float)OUTS;
    float stepy = toty / (float)OUTS;
    float tkx = ((float)t + 0.5f) * stepx;
    float tky = ((float)t + 0.5f) * stepy;

    g_px[n * OUTS + t] = inv_cdf_one(cx, tkx, dx);
    g_py[n * OUTS + t] = inv_cdf_one(cy, tky, dy);
}

// LSU-floor-optimized sampler (R14 winner, unchanged): each thread owns 2
// CONSECUTIVE px and RPT=4 rows; 12 LDG.32/px gathers; STG.64/STG.128 stores
// with __stcs streaming policy.
// grid: (OUTS/256 jtiles, OUTS/RPT rowtiles, N); block 128.
__global__ void __launch_bounds__(128) sample_kernel(const float* __restrict__ data,
                                                     float* __restrict__ out_s,
                                                     float4* __restrict__ out_g) {
    int tx = threadIdx.x;                      // 0..127
    int j0 = (blockIdx.x * 128 + tx) * 2;      // first of 2 consecutive px
    int i0 = blockIdx.y * RPT;                 // first output row
    int n = blockIdx.z;

    // px coords for the 2 pixels (one LDG.64)
    float2 px2 = __ldg((const float2*)&g_px[n * OUTS + j0]);
    float pxv[2] = {px2.x, px2.y};
    int x0[2], x1[2];
    float wx[2];
    #pragma unroll
    for (int q = 0; q < 2; ++q) {
        float ix = (pxv[q] + 1.f) * 0.5f * (float)(WW - 1);
        float fx = floorf(ix);
        wx[q] = ix - fx;
        x0[q] = min(max((int)fx, 0), WW - 1);
        x1[q] = min(x0[q] + 1, WW - 1);
    }

    // py coords for RPT rows (one LDG.128; i0 is 4-aligned)
    float4 py4 = __ldg((const float4*)&g_py[n * OUTS + i0]);
    float pyv[RPT] = {py4.x, py4.y, py4.z, py4.w};
    float wy[RPT];
    int y0[RPT], y1[RPT];
    #pragma unroll
    for (int r = 0; r < RPT; ++r) {
        float iy = (pyv[r] + 1.f) * 0.5f * (float)(HH - 1);
        float fy = floorf(iy);
        wy[r] = iy - fy;
        int yy0 = min(max((int)fy, 0), HH - 1);
        y0[r] = yy0;
        y1[r] = min(yy0 + 1, HH - 1);
    }

    const float* img = data + (size_t)n * CC * HH * WW;

    #pragma unroll
    for (int r = 0; r < RPT; ++r) {
        float v00[CC][2], v01[CC][2], v10[CC][2], v11[CC][2];
        #pragma unroll
        for (int c = 0; c < CC; ++c) {
            const float* ch = img + (size_t)c * HH * WW;
            const float* r0p = ch + (size_t)y0[r] * WW;
            const float* r1p = ch + (size_t)y1[r] * WW;
            #pragma unroll
            for (int q = 0; q < 2; ++q) {
                v00[c][q] = __ldg(r0p + x0[q]);
                v01[c][q] = __ldg(r0p + x1[q]);
                v10[c][q] = __ldg(r1p + x0[q]);
                v11[c][q] = __ldg(r1p + x1[q]);
            }
        }
        float omwy = 1.f - wy[r];
        #pragma unroll
        for (int c = 0; c < CC; ++c) {
            float res[2];
            #pragma unroll
            for (int q = 0; q < 2; ++q) {
                float omwx = 1.f - wx[q];
                float top = v00[c][q] * omwx + v01[c][q] * wx[q];
                float bot = v10[c][q] * omwx + v11[c][q] * wx[q];
                res[q] = top * omwy + bot * wy[r];
            }
            float* o = out_s + (((size_t)n * CC + c) * HH + i0 + r) * WW + j0;
            __stcs((float2*)o, make_float2(res[0], res[1]));
        }
        float4* g = out_g + (((size_t)n * OUTS + i0 + r) * OUTS + j0) / 2;
        __stcs(g, make_float4(pxv[0], pyv[r], pxv[1], pyv[r]));
    }
}

extern "C" void kernel_launch(void* const* d_in, const int* in_sizes, int n_in,
                              void* d_out, int out_size) {
    const float* data = (const float*)d_in[0];
    const float* attx = (const float*)d_in[1];
    const float* atty = (const float*)d_in[2];

    int N = in_sizes[1] / AA;   // attx is (N, 512, 1)

    float* out = (float*)d_out;
    float* out_s = out;                                        // (N, C, 512, 512)
    float4* out_g = (float4*)(out + (size_t)N * CC * HH * WW); // (N, 512, 512, 2)

    prep_kernel<<<N, 512>>>(attx, atty);
    dim3 block(128);
    dim3 grid(OUTS / 256, OUTS / RPT, N);
    sample_kernel<<<grid, block>>>(data, out_s, out_g);
}

// round 16
// speedup vs baseline: 1.2507x; 1.0052x over previous
#include <cuda_runtime.h>
#include <cstdint>

#define AA 512      // attention length
#define OUTS 512    // out_size
#define HH 512
#define WW 512
#define CC 3
#define NMAX 32
#define RPT 4       // rows per thread (sample kernel)

// scratch (allocation-free rule: device globals)
__device__ float g_px[NMAX * OUTS];
__device__ float g_py[NMAX * OUTS];

__device__ __forceinline__ float warpSum(float v) {
    #pragma unroll
    for (int o = 16; o; o >>= 1) v += __shfl_xor_sync(0xffffffffu, v, o);
    return v;
}
__device__ __forceinline__ float warpMax(float v) {
    #pragma unroll
    for (int o = 16; o; o >>= 1) v = fmaxf(v, __shfl_xor_sync(0xffffffffu, v, o));
    return v;
}

// fused block reduction: sums of (a,b) and maxes of (c,d), one barrier round
__device__ void blockRed4(float a, float b, float c, float d, volatile float* sbuf,
                          float* ra, float* rb, float* rc, float* rd) {
    int lane = threadIdx.x & 31, w = threadIdx.x >> 5;
    a = warpSum(a); b = warpSum(b); c = warpMax(c); d = warpMax(d);
    if (lane == 0) { sbuf[w] = a; sbuf[32 + w] = b; sbuf[64 + w] = c; sbuf[96 + w] = d; }
    __syncthreads();
    if (w == 0) {
        float x = (lane < 16) ? sbuf[lane] : 0.f;
        float y = (lane < 16) ? sbuf[32 + lane] : 0.f;
        float z = (lane < 16) ? sbuf[64 + lane] : -3.4e38f;
        float u = (lane < 16) ? sbuf[96 + lane] : -3.4e38f;
        x = warpSum(x); y = warpSum(y); z = warpMax(z); u = warpMax(u);
        if (lane == 0) { sbuf[0] = x; sbuf[32] = y; sbuf[64] = z; sbuf[96] = u; }
    }
    __syncthreads();
    *ra = sbuf[0]; *rb = sbuf[32]; *rc = sbuf[64]; *rd = sbuf[96];
    __syncthreads();
}

// fused block sum of two values (512 threads), one barrier round
__device__ void blockSum2(float a, float b, volatile float* sbuf, float* ra, float* rb) {
    int lane = threadIdx.x & 31, w = threadIdx.x >> 5;
    a = warpSum(a); b = warpSum(b);
    if (lane == 0) { sbuf[w] = a; sbuf[32 + w] = b; }
    __syncthreads();
    if (w == 0) {
        float x = (lane < 16) ? sbuf[lane] : 0.f;
        float y = (lane < 16) ? sbuf[32 + lane] : 0.f;
        x = warpSum(x); y = warpSum(y);
        if (lane == 0) { sbuf[0] = x; sbuf[32] = y; }
    }
    __syncthreads();
    *ra = sbuf[0]; *rb = sbuf[32];
    __syncthreads();
}

// fused inclusive block scan of two 512-value sequences -> outa[tid], outb[tid]
__device__ void blockScan2(float a, float b, float* outa, float* outb, volatile float* sbuf) {
    int lane = threadIdx.x & 31, w = threadIdx.x >> 5;
    float sa = a, sb = b;
    #pragma unroll
    for (int o = 1; o < 32; o <<= 1) {
        float ta = __shfl_up_sync(0xffffffffu, sa, o);
        float tb = __shfl_up_sync(0xffffffffu, sb, o);
        if (lane >= o) { sa += ta; sb += tb; }
    }
    if (lane == 31) { sbuf[w] = sa; sbuf[32 + w] = sb; }
    __syncthreads();
    if (w == 0 && lane < 16) {
        float wa = sbuf[lane], wb = sbuf[32 + lane];
        #pragma unroll
        for (int o = 1; o < 16; o <<= 1) {
            float ta = __shfl_up_sync(0x0000ffffu, wa, o);
            float tb = __shfl_up_sync(0x0000ffffu, wb, o);
            if (lane >= o) { wa += ta; wb += tb; }
        }
        sbuf[lane] = wa; sbuf[32 + lane] = wb;
    }
    __syncthreads();
    float offa = (w > 0) ? sbuf[w - 1] : 0.f;
    float offb = (w > 0) ? sbuf[32 + w - 1] : 0.f;
    outa[threadIdx.x] = sa + offa;
    outb[threadIdx.x] = sb + offb;
    __syncthreads();
}

// searchsorted-left on corrected cdf c_eff[m] = c[m] + (m+1)*dcor
__device__ __forceinline__ float inv_cdf_one(const float* c, float tk, float dcor) {
    int l = 0, h = AA;
    #pragma unroll
    for (int it = 0; it < 10; ++it) {
        if (l < h) {
            int m = (l + h) >> 1;
            float cm = c[m] + (float)(m + 1) * dcor;
            if (cm < tk) l = m + 1; else h = m;
        }
    }
    int j = min(l, AA - 1);
    float cp = (j > 0) ? (c[j - 1] + (float)j * dcor) : 0.f;
    float cj = c[j] + (float)(j + 1) * dcor;
    float dens = cj - cp;
    float p = (float)j + (tk - cp) / fmaxf(dens, 1e-6f);
    return 2.f * p / (float)AA - 1.f;
}

// prep with analytic max tracking: 6 barrier rounds total; signals PDL
// dependents after writing g_px/g_py.
__global__ void __launch_bounds__(512) prep_kernel(const float* __restrict__ attx,
                                                   const float* __restrict__ atty) {
    __shared__ float sbuf[128];
    __shared__ float cx[AA];
    __shared__ float cy[AA];
    int n = blockIdx.x;
    int t = threadIdx.x;

    float ax = attx[n * AA + t];
    float ay = atty[n * AA + t];

    float sax, say, mxx, mxy;
    blockRed4(ax, ay, ax, ay, sbuf, &sax, &say, &mxx, &mxy);
    ax = ax / sax * (float)OUTS;
    ay = ay / say * (float)OUTS;
    mxx = mxx / sax * (float)OUTS;   // exact: monotone scaling, attained at argmax
    mxy = mxy / say * (float)OUTS;

    const float thr0 = 4.0f * (float)OUTS / (float)AA;  // DENSE*out/A
    #pragma unroll
    for (int it = 0; it < 5; ++it) {
        float tt = fminf(mxx, mxy);
        if (it == 0) tt = fminf(tt, thr0);
        ax = fminf(ax, tt);
        ay = fminf(ay, tt);
        if (it < 4) {
            float ssx, ssy;
            blockSum2(ax, ay, sbuf, &ssx, &ssy);
            float dx = ((float)OUTS - ssx) / (float)AA;
            float dy = ((float)OUTS - ssy) / (float)AA;
            ax += dx; ay += dy;
            mxx = fminf(mxx, tt) + dx;   // exact analytic max update
            mxy = fminf(mxy, tt) + dy;
        }
    }

    // scan of CLIPPED values (5th renorm folded in via dx correction)
    blockScan2(ax, ay, cx, cy, sbuf);
    float dx = ((float)OUTS - cx[AA - 1]) / (float)AA;
    float dy = ((float)OUTS - cy[AA - 1]) / (float)AA;
    float totx = cx[AA - 1] + (float)AA * dx;
    float toty = cy[AA - 1] + (float)AA * dy;

    float stepx = totx / (float)OUTS;
    float stepy = toty / (float)OUTS;
    float tkx = ((float)t + 0.5f) * stepx;
    float tky = ((float)t + 0.5f) * stepy;

    g_px[n * OUTS + t] = inv_cdf_one(cx, tkx, dx);
    g_py[n * OUTS + t] = inv_cdf_one(cy, tky, dy);

    // PDL: allow dependent grid's griddepcontrol.wait to pass once all CTAs
    // have written their g_px/g_py slices.
    asm volatile("griddepcontrol.launch_dependents;" ::: "memory");
}

// LSU-floor-optimized sampler (R14/R15 winner) + PDL prelude overlap:
// index math runs before griddepcontrol.wait; g_px/g_py reads after.
__global__ void __launch_bounds__(128) sample_kernel(const float* __restrict__ data,
                                                     float* __restrict__ out_s,
                                                     float4* __restrict__ out_g) {
    int tx = threadIdx.x;                      // 0..127
    int j0 = (blockIdx.x * 128 + tx) * 2;      // first of 2 consecutive px
    int i0 = blockIdx.y * RPT;                 // first output row
    int n = blockIdx.z;

    const float* img = data + (size_t)n * CC * HH * WW;
    const float* px_p = &g_px[n * OUTS + j0];
    const float* py_p = &g_py[n * OUTS + i0];

    // wait for prep's g_px/g_py (overlaps launch latency with prep execution)
    asm volatile("griddepcontrol.wait;" ::: "memory");

    // px coords for the 2 pixels (one LDG.64)
    float2 px2 = __ldg((const float2*)px_p);
    float pxv[2] = {px2.x, px2.y};
    int x0[2], x1[2];
    float wx[2];
    #pragma unroll
    for (int q = 0; q < 2; ++q) {
        float ix = (pxv[q] + 1.f) * 0.5f * (float)(WW - 1);
        float fx = floorf(ix);
        wx[q] = ix - fx;
        x0[q] = min(max((int)fx, 0), WW - 1);
        x1[q] = min(x0[q] + 1, WW - 1);
    }

    // py coords for RPT rows (one LDG.128; i0 is 4-aligned)
    float4 py4 = __ldg((const float4*)py_p);
    float pyv[RPT] = {py4.x, py4.y, py4.z, py4.w};
    float wy[RPT];
    int y0[RPT], y1[RPT];
    #pragma unroll
    for (int r = 0; r < RPT; ++r) {
        float iy = (pyv[r] + 1.f) * 0.5f * (float)(HH - 1);
        float fy = floorf(iy);
        wy[r] = iy - fy;
        int yy0 = min(max((int)fy, 0), HH - 1);
        y0[r] = yy0;
        y1[r] = min(yy0 + 1, HH - 1);
    }

    #pragma unroll
    for (int r = 0; r < RPT; ++r) {
        float v00[CC][2], v01[CC][2], v10[CC][2], v11[CC][2];
        #pragma unroll
        for (int c = 0; c < CC; ++c) {
            const float* ch = img + (size_t)c * HH * WW;
            const float* r0p = ch + (size_t)y0[r] * WW;
            const float* r1p = ch + (size_t)y1[r] * WW;
            #pragma unroll
            for (int q = 0; q < 2; ++q) {
                v00[c][q] = __ldg(r0p + x0[q]);
                v01[c][q] = __ldg(r0p + x1[q]);
                v10[c][q] = __ldg(r1p + x0[q]);
                v11[c][q] = __ldg(r1p + x1[q]);
            }
        }
        float omwy = 1.f - wy[r];
        #pragma unroll
        for (int c = 0; c < CC; ++c) {
            float res[2];
            #pragma unroll
            for (int q = 0; q < 2; ++q) {
                float omwx = 1.f - wx[q];
                float top = v00[c][q] * omwx + v01[c][q] * wx[q];
                float bot = v10[c][q] * omwx + v11[c][q] * wx[q];
                res[q] = top * omwy + bot * wy[r];
            }
            float* o = out_s + (((size_t)n * CC + c) * HH + i0 + r) * WW + j0;
            __stcs((float2*)o, make_float2(res[0], res[1]));
        }
        float4* g = out_g + (((size_t)n * OUTS + i0 + r) * OUTS + j0) / 2;
        __stcs(g, make_float4(pxv[0], pyv[r], pxv[1], pyv[r]));
    }
}

extern "C" void kernel_launch(void* const* d_in, const int* in_sizes, int n_in,
                              void* d_out, int out_size) {
    const float* data = (const float*)d_in[0];
    const float* attx = (const float*)d_in[1];
    const float* atty = (const float*)d_in[2];

    int N = in_sizes[1] / AA;   // attx is (N, 512, 1)

    float* out = (float*)d_out;
    float* out_s = out;                                        // (N, C, 512, 512)
    float4* out_g = (float4*)(out + (size_t)N * CC * HH * WW); // (N, 512, 512, 2)

    prep_kernel<<<N, 512>>>(attx, atty);

    // sample launched with Programmatic Stream Serialization: it may begin
    // (prelude) while prep is still running; griddepcontrol.wait gates the
    // g_px/g_py reads.
    cudaLaunchConfig_t cfg = {};
    cfg.gridDim = dim3(OUTS / 256, OUTS / RPT, N);
    cfg.blockDim = dim3(128);
    cudaLaunchAttribute attrs[1];
    attrs[0].id = cudaLaunchAttributeProgrammaticStreamSerialization;
    attrs[0].val.programmaticStreamSerializationAllowed = 1;
    cfg.attrs = attrs;
    cfg.numAttrs = 1;
    cudaLaunchKernelEx(&cfg, sample_kernel, data, out_s, out_g);
}